// round 5
// baseline (speedup 1.0000x reference)
#include <cuda_runtime.h>

// Problem constants
#define kB   4
#define kS   2048
#define kDIN 1024
#define kH   16
#define kD   64
#define kHD  1024
#define kM   (kB * kS)   // 8192

// Scratch (device globals — no allocation allowed)
__device__ float g_q[(size_t)kB * kH * kS * kD];   // [B,H,S,D]
__device__ float g_k[(size_t)kB * kH * kS * kD];
__device__ float g_v[(size_t)kB * kH * kS * kD];
__device__ float g_att[(size_t)kM * kHD];          // [B*S, H*D]

// ---------------------------------------------------------------------------
// Kernel 1: fused QKV projection.
// Grid: (kM/64, 48). blockIdx.y: mat = y>>4 (0=q,1=k,2=v), h = y&15.
// Each block computes a 64(M) x 64(N) tile of X @ W[:, h*64 : h*64+64].
// BK = 16. 256 threads as 16x16, 4x4 register tile per thread.
// X tile stored transposed in smem: Xs[k][m]; W tile natural: Ws[k][n].
// ---------------------------------------------------------------------------
__global__ __launch_bounds__(256) void qkv_kernel(
    const float* __restrict__ x,
    const float* __restrict__ wq, const float* __restrict__ bq,
    const float* __restrict__ wk, const float* __restrict__ bk,
    const float* __restrict__ wv, const float* __restrict__ bv)
{
    __shared__ float Xs[16][64];
    __shared__ float Ws[16][64];

    const int tid = threadIdx.x;
    const int tx = tid & 15;
    const int ty = tid >> 4;

    const int m0  = blockIdx.x * 64;
    const int yb  = blockIdx.y;
    const int mat = yb >> 4;
    const int h   = yb & 15;

    const float* w    = (mat == 0) ? wq : (mat == 1) ? wk : wv;
    const float* bias = (mat == 0) ? bq : (mat == 1) ? bk : bv;
    float* dst        = (mat == 0) ? g_q : (mat == 1) ? g_k : g_v;
    const int n0 = h * 64;

    // loader indices
    const int xr  = tid >> 2;        // 0..63 (tile row for X)
    const int xc4 = tid & 3;         // 0..3  (float4 col within 16-wide K tile)
    const int wr  = tid >> 4;        // 0..15 (tile row for W = k index)
    const int wc4 = tid & 15;        // 0..15 (float4 col within 64-wide N tile)

    float acc[4][4] = {};

    for (int kk = 0; kk < kDIN; kk += 16) {
        // X tile -> transposed Xs[k][m]
        float4 xv = *(const float4*)(x + (size_t)(m0 + xr) * kDIN + kk + xc4 * 4);
        Xs[xc4 * 4 + 0][xr] = xv.x;
        Xs[xc4 * 4 + 1][xr] = xv.y;
        Xs[xc4 * 4 + 2][xr] = xv.z;
        Xs[xc4 * 4 + 3][xr] = xv.w;
        // W tile natural
        *(float4*)&Ws[wr][wc4 * 4] =
            *(const float4*)(w + (size_t)(kk + wr) * kHD + n0 + wc4 * 4);
        __syncthreads();

        #pragma unroll
        for (int k = 0; k < 16; k++) {
            float4 a = *(const float4*)&Xs[k][ty * 4];
            float4 b = *(const float4*)&Ws[k][tx * 4];
            float av[4] = {a.x, a.y, a.z, a.w};
            float bv4[4] = {b.x, b.y, b.z, b.w};
            #pragma unroll
            for (int i = 0; i < 4; i++)
                #pragma unroll
                for (int j = 0; j < 4; j++)
                    acc[i][j] += av[i] * bv4[j];
        }
        __syncthreads();
    }

    // epilogue: write to [B,H,S,D]
    #pragma unroll
    for (int i = 0; i < 4; i++) {
        const int m = m0 + ty * 4 + i;
        const int b = m / kS;
        const int s = m % kS;
        float* drow = dst + ((size_t)(b * kH + h) * kS + s) * kD;
        #pragma unroll
        for (int j = 0; j < 4; j++) {
            const int d = tx * 4 + j;
            drow[d] = acc[i][j] + bias[n0 + d];
        }
    }
}

// ---------------------------------------------------------------------------
// Kernel 2: flash attention. Grid: (kS/64, kH, kB). 256 threads (16x16).
// Q,K in smem d-major: Qs[d][row], Ks[d][row]. V,P row-major.
// Online softmax, 4 query rows x 4 cols per thread.
// ---------------------------------------------------------------------------
__global__ __launch_bounds__(256) void attn_kernel()
{
    __shared__ float Qs[64][64];   // [d][qrow], pre-scaled by 1/sqrt(D)
    __shared__ float Ks[64][64];   // [d][krow]
    __shared__ float Vs[64][64];   // [krow][d]
    __shared__ float Ps[64][64];   // [qrow][krow]

    const int tid = threadIdx.x;
    const int tx = tid & 15;
    const int ty = tid >> 4;

    const int qb = blockIdx.x;
    const int h  = blockIdx.y;
    const int b  = blockIdx.z;

    const float* qp = g_q + ((size_t)(b * kH + h) * kS + qb * 64) * kD;
    const float* kp = g_k + (size_t)(b * kH + h) * kS * kD;
    const float* vp = g_v + (size_t)(b * kH + h) * kS * kD;

    // Load Q transposed (mapping B: c4 = tid>>4, r = (tid&15)+p*16), scaled.
    #pragma unroll
    for (int p = 0; p < 4; p++) {
        const int r  = (tid & 15) + p * 16;
        const int c4 = tid >> 4;
        float4 qv = *(const float4*)(qp + (size_t)r * kD + c4 * 4);
        Qs[c4 * 4 + 0][r] = qv.x * 0.125f;
        Qs[c4 * 4 + 1][r] = qv.y * 0.125f;
        Qs[c4 * 4 + 2][r] = qv.z * 0.125f;
        Qs[c4 * 4 + 3][r] = qv.w * 0.125f;
    }

    float m_i[4], l_i[4], o_acc[4][4];
    #pragma unroll
    for (int i = 0; i < 4; i++) {
        m_i[i] = -1e30f;
        l_i[i] = 0.f;
        #pragma unroll
        for (int j = 0; j < 4; j++) o_acc[i][j] = 0.f;
    }
    __syncthreads();

    for (int kt = 0; kt < kS / 64; kt++) {
        // Load K transposed, V natural
        #pragma unroll
        for (int p = 0; p < 4; p++) {
            const int r  = (tid & 15) + p * 16;
            const int c4 = tid >> 4;
            float4 kv = *(const float4*)(kp + (size_t)(kt * 64 + r) * kD + c4 * 4);
            Ks[c4 * 4 + 0][r] = kv.x;
            Ks[c4 * 4 + 1][r] = kv.y;
            Ks[c4 * 4 + 2][r] = kv.z;
            Ks[c4 * 4 + 3][r] = kv.w;
        }
        #pragma unroll
        for (int p = 0; p < 4; p++) {
            const int r  = (tid >> 4) + p * 16;
            const int c4 = tid & 15;
            *(float4*)&Vs[r][c4 * 4] =
                *(const float4*)(vp + (size_t)(kt * 64 + r) * kD + c4 * 4);
        }
        __syncthreads();

        // S tile: s[i][j] = sum_d Qs[d][qr] * Ks[d][kc]
        float sv[4][4] = {};
        #pragma unroll 8
        for (int d = 0; d < 64; d++) {
            float4 a = *(const float4*)&Qs[d][ty * 4];
            float4 bb = *(const float4*)&Ks[d][tx * 4];
            float av[4] = {a.x, a.y, a.z, a.w};
            float bv4[4] = {bb.x, bb.y, bb.z, bb.w};
            #pragma unroll
            for (int i = 0; i < 4; i++)
                #pragma unroll
                for (int j = 0; j < 4; j++)
                    sv[i][j] += av[i] * bv4[j];
        }

        // Row max (reduce over this thread's 4 cols, then across tx via shfl)
        float tmax[4];
        #pragma unroll
        for (int i = 0; i < 4; i++) {
            tmax[i] = fmaxf(fmaxf(sv[i][0], sv[i][1]), fmaxf(sv[i][2], sv[i][3]));
        }
        #pragma unroll
        for (int msk = 1; msk < 16; msk <<= 1) {
            #pragma unroll
            for (int i = 0; i < 4; i++)
                tmax[i] = fmaxf(tmax[i], __shfl_xor_sync(0xffffffffu, tmax[i], msk));
        }

        float sc[4], rsum[4];
        #pragma unroll
        for (int i = 0; i < 4; i++) {
            const float mnew = fmaxf(m_i[i], tmax[i]);
            sc[i] = __expf(m_i[i] - mnew);
            m_i[i] = mnew;
            rsum[i] = 0.f;
            #pragma unroll
            for (int j = 0; j < 4; j++) {
                sv[i][j] = __expf(sv[i][j] - mnew);
                rsum[i] += sv[i][j];
            }
        }
        #pragma unroll
        for (int msk = 1; msk < 16; msk <<= 1) {
            #pragma unroll
            for (int i = 0; i < 4; i++)
                rsum[i] += __shfl_xor_sync(0xffffffffu, rsum[i], msk);
        }
        #pragma unroll
        for (int i = 0; i < 4; i++) {
            l_i[i] = l_i[i] * sc[i] + rsum[i];
            #pragma unroll
            for (int j = 0; j < 4; j++) o_acc[i][j] *= sc[i];
        }

        // Write P row-major (conflict-free float4 store per row)
        #pragma unroll
        for (int i = 0; i < 4; i++) {
            float4 pv4 = make_float4(sv[i][0], sv[i][1], sv[i][2], sv[i][3]);
            *(float4*)&Ps[ty * 4 + i][tx * 4] = pv4;
        }
        __syncthreads();

        // O += P @ V : inner over key index c, float4-blocked
        #pragma unroll 4
        for (int c4 = 0; c4 < 16; c4++) {
            float4 pr[4];
            #pragma unroll
            for (int i = 0; i < 4; i++)
                pr[i] = *(const float4*)&Ps[ty * 4 + i][c4 * 4];
            float4 vr[4];
            #pragma unroll
            for (int cc = 0; cc < 4; cc++)
                vr[cc] = *(const float4*)&Vs[c4 * 4 + cc][tx * 4];
            #pragma unroll
            for (int i = 0; i < 4; i++) {
                float pi[4] = {pr[i].x, pr[i].y, pr[i].z, pr[i].w};
                #pragma unroll
                for (int cc = 0; cc < 4; cc++) {
                    float vv[4] = {vr[cc].x, vr[cc].y, vr[cc].z, vr[cc].w};
                    #pragma unroll
                    for (int j = 0; j < 4; j++)
                        o_acc[i][j] += pi[cc] * vv[j];
                }
            }
        }
        __syncthreads();
    }

    // Epilogue: normalize and write to g_att [B*S, H*D]
    #pragma unroll
    for (int i = 0; i < 4; i++) {
        const float inv = 1.0f / l_i[i];
        const int s = qb * 64 + ty * 4 + i;
        float* orow = g_att + ((size_t)b * kS + s) * kHD + h * kD;
        #pragma unroll
        for (int j = 0; j < 4; j++)
            orow[tx * 4 + j] = o_acc[i][j] * inv;
    }
}

// ---------------------------------------------------------------------------
// Kernel 3: output projection. g_att[8192,1024] @ wo[1024,64] + bo -> out
// Grid: 128 blocks; each computes a 64x64 tile (full N). BK=16.
// ---------------------------------------------------------------------------
__global__ __launch_bounds__(256) void oproj_kernel(
    const float* __restrict__ wo, const float* __restrict__ bo,
    float* __restrict__ out)
{
    __shared__ float Xs[16][64];
    __shared__ float Ws[16][64];

    const int tid = threadIdx.x;
    const int tx = tid & 15;
    const int ty = tid >> 4;
    const int m0 = blockIdx.x * 64;

    const int xr  = tid >> 2;
    const int xc4 = tid & 3;
    const int wr  = tid >> 4;
    const int wc4 = tid & 15;

    float acc[4][4] = {};

    for (int kk = 0; kk < kHD; kk += 16) {
        float4 xv = *(const float4*)(g_att + (size_t)(m0 + xr) * kHD + kk + xc4 * 4);
        Xs[xc4 * 4 + 0][xr] = xv.x;
        Xs[xc4 * 4 + 1][xr] = xv.y;
        Xs[xc4 * 4 + 2][xr] = xv.z;
        Xs[xc4 * 4 + 3][xr] = xv.w;
        *(float4*)&Ws[wr][wc4 * 4] =
            *(const float4*)(wo + (size_t)(kk + wr) * kD + wc4 * 4);
        __syncthreads();

        #pragma unroll
        for (int k = 0; k < 16; k++) {
            float4 a = *(const float4*)&Xs[k][ty * 4];
            float4 b = *(const float4*)&Ws[k][tx * 4];
            float av[4] = {a.x, a.y, a.z, a.w};
            float bv4[4] = {b.x, b.y, b.z, b.w};
            #pragma unroll
            for (int i = 0; i < 4; i++)
                #pragma unroll
                for (int j = 0; j < 4; j++)
                    acc[i][j] += av[i] * bv4[j];
        }
        __syncthreads();
    }

    #pragma unroll
    for (int i = 0; i < 4; i++) {
        const int m = m0 + ty * 4 + i;
        #pragma unroll
        for (int j = 0; j < 4; j++) {
            const int d = tx * 4 + j;
            out[(size_t)m * kD + d] = acc[i][j] + bo[d];
        }
    }
}

// ---------------------------------------------------------------------------
extern "C" void kernel_launch(void* const* d_in, const int* in_sizes, int n_in,
                              void* d_out, int out_size)
{
    const float* x  = (const float*)d_in[0];
    const float* wq = (const float*)d_in[1];
    const float* bq = (const float*)d_in[2];
    const float* wk = (const float*)d_in[3];
    const float* bk = (const float*)d_in[4];
    const float* wv = (const float*)d_in[5];
    const float* bv = (const float*)d_in[6];
    const float* wo = (const float*)d_in[7];
    const float* bo = (const float*)d_in[8];
    float* out = (float*)d_out;

    qkv_kernel<<<dim3(kM / 64, 48), 256>>>(x, wq, bq, wk, bk, wv, bv);
    attn_kernel<<<dim3(kS / 64, kH, kB), 256>>>();
    oproj_kernel<<<dim3(kM / 64), 256>>>(wo, bo, out);
}

// round 6
// speedup vs baseline: 1.0007x; 1.0007x over previous
#include <cuda_runtime.h>

// Problem constants
#define kB   4
#define kS   2048
#define kDIN 1024
#define kH   16
#define kD   64
#define kHD  1024
#define kM   (kB * kS)   // 8192

// Scratch (device globals — no allocation allowed)
__device__ float g_q[(size_t)kB * kH * kS * kD];   // [B,H,S,D]
__device__ float g_k[(size_t)kB * kH * kS * kD];
__device__ float g_v[(size_t)kB * kH * kS * kD];
__device__ float g_att[(size_t)kM * kHD];          // [B*S, H*D]

// ---------------------------------------------------------------------------
// Kernel 1: fused QKV projection.
// Grid: (kM/64, 48). blockIdx.y: mat = y>>4 (0=q,1=k,2=v), h = y&15.
// Each block computes a 64(M) x 64(N) tile of X @ W[:, h*64 : h*64+64].
// BK = 16. 256 threads as 16x16, 4x4 register tile per thread.
// X tile stored transposed in smem: Xs[k][m]; W tile natural: Ws[k][n].
// ---------------------------------------------------------------------------
__global__ __launch_bounds__(256) void qkv_kernel(
    const float* __restrict__ x,
    const float* __restrict__ wq, const float* __restrict__ bq,
    const float* __restrict__ wk, const float* __restrict__ bk,
    const float* __restrict__ wv, const float* __restrict__ bv)
{
    __shared__ float Xs[16][64];
    __shared__ float Ws[16][64];

    const int tid = threadIdx.x;
    const int tx = tid & 15;
    const int ty = tid >> 4;

    const int m0  = blockIdx.x * 64;
    const int yb  = blockIdx.y;
    const int mat = yb >> 4;
    const int h   = yb & 15;

    const float* w    = (mat == 0) ? wq : (mat == 1) ? wk : wv;
    const float* bias = (mat == 0) ? bq : (mat == 1) ? bk : bv;
    float* dst        = (mat == 0) ? g_q : (mat == 1) ? g_k : g_v;
    const int n0 = h * 64;

    // loader indices
    const int xr  = tid >> 2;        // 0..63 (tile row for X)
    const int xc4 = tid & 3;         // 0..3  (float4 col within 16-wide K tile)
    const int wr  = tid >> 4;        // 0..15 (tile row for W = k index)
    const int wc4 = tid & 15;        // 0..15 (float4 col within 64-wide N tile)

    float acc[4][4] = {};

    for (int kk = 0; kk < kDIN; kk += 16) {
        // X tile -> transposed Xs[k][m]
        float4 xv = *(const float4*)(x + (size_t)(m0 + xr) * kDIN + kk + xc4 * 4);
        Xs[xc4 * 4 + 0][xr] = xv.x;
        Xs[xc4 * 4 + 1][xr] = xv.y;
        Xs[xc4 * 4 + 2][xr] = xv.z;
        Xs[xc4 * 4 + 3][xr] = xv.w;
        // W tile natural
        *(float4*)&Ws[wr][wc4 * 4] =
            *(const float4*)(w + (size_t)(kk + wr) * kHD + n0 + wc4 * 4);
        __syncthreads();

        #pragma unroll
        for (int k = 0; k < 16; k++) {
            float4 a = *(const float4*)&Xs[k][ty * 4];
            float4 b = *(const float4*)&Ws[k][tx * 4];
            float av[4] = {a.x, a.y, a.z, a.w};
            float bv4[4] = {b.x, b.y, b.z, b.w};
            #pragma unroll
            for (int i = 0; i < 4; i++)
                #pragma unroll
                for (int j = 0; j < 4; j++)
                    acc[i][j] += av[i] * bv4[j];
        }
        __syncthreads();
    }

    // epilogue: write to [B,H,S,D]
    #pragma unroll
    for (int i = 0; i < 4; i++) {
        const int m = m0 + ty * 4 + i;
        const int b = m / kS;
        const int s = m % kS;
        float* drow = dst + ((size_t)(b * kH + h) * kS + s) * kD;
        #pragma unroll
        for (int j = 0; j < 4; j++) {
            const int d = tx * 4 + j;
            drow[d] = acc[i][j] + bias[n0 + d];
        }
    }
}

// ---------------------------------------------------------------------------
// Kernel 2: flash attention. Grid: (kS/64, kH, kB). 256 threads (16x16).
// Q,K in smem d-major: Qs[d][row], Ks[d][row]. V,P row-major.
// Online softmax, 4 query rows x 4 cols per thread.
// ---------------------------------------------------------------------------
__global__ __launch_bounds__(256) void attn_kernel()
{
    __shared__ float Qs[64][64];   // [d][qrow], pre-scaled by 1/sqrt(D)
    __shared__ float Ks[64][64];   // [d][krow]
    __shared__ float Vs[64][64];   // [krow][d]
    __shared__ float Ps[64][64];   // [qrow][krow]

    const int tid = threadIdx.x;
    const int tx = tid & 15;
    const int ty = tid >> 4;

    const int qb = blockIdx.x;
    const int h  = blockIdx.y;
    const int b  = blockIdx.z;

    const float* qp = g_q + ((size_t)(b * kH + h) * kS + qb * 64) * kD;
    const float* kp = g_k + (size_t)(b * kH + h) * kS * kD;
    const float* vp = g_v + (size_t)(b * kH + h) * kS * kD;

    // Load Q transposed (mapping B: c4 = tid>>4, r = (tid&15)+p*16), scaled.
    #pragma unroll
    for (int p = 0; p < 4; p++) {
        const int r  = (tid & 15) + p * 16;
        const int c4 = tid >> 4;
        float4 qv = *(const float4*)(qp + (size_t)r * kD + c4 * 4);
        Qs[c4 * 4 + 0][r] = qv.x * 0.125f;
        Qs[c4 * 4 + 1][r] = qv.y * 0.125f;
        Qs[c4 * 4 + 2][r] = qv.z * 0.125f;
        Qs[c4 * 4 + 3][r] = qv.w * 0.125f;
    }

    float m_i[4], l_i[4], o_acc[4][4];
    #pragma unroll
    for (int i = 0; i < 4; i++) {
        m_i[i] = -1e30f;
        l_i[i] = 0.f;
        #pragma unroll
        for (int j = 0; j < 4; j++) o_acc[i][j] = 0.f;
    }
    __syncthreads();

    for (int kt = 0; kt < kS / 64; kt++) {
        // Load K transposed, V natural
        #pragma unroll
        for (int p = 0; p < 4; p++) {
            const int r  = (tid & 15) + p * 16;
            const int c4 = tid >> 4;
            float4 kv = *(const float4*)(kp + (size_t)(kt * 64 + r) * kD + c4 * 4);
            Ks[c4 * 4 + 0][r] = kv.x;
            Ks[c4 * 4 + 1][r] = kv.y;
            Ks[c4 * 4 + 2][r] = kv.z;
            Ks[c4 * 4 + 3][r] = kv.w;
        }
        #pragma unroll
        for (int p = 0; p < 4; p++) {
            const int r  = (tid >> 4) + p * 16;
            const int c4 = tid & 15;
            *(float4*)&Vs[r][c4 * 4] =
                *(const float4*)(vp + (size_t)(kt * 64 + r) * kD + c4 * 4);
        }
        __syncthreads();

        // S tile: s[i][j] = sum_d Qs[d][qr] * Ks[d][kc]
        float sv[4][4] = {};
        #pragma unroll 8
        for (int d = 0; d < 64; d++) {
            float4 a = *(const float4*)&Qs[d][ty * 4];
            float4 bb = *(const float4*)&Ks[d][tx * 4];
            float av[4] = {a.x, a.y, a.z, a.w};
            float bv4[4] = {bb.x, bb.y, bb.z, bb.w};
            #pragma unroll
            for (int i = 0; i < 4; i++)
                #pragma unroll
                for (int j = 0; j < 4; j++)
                    sv[i][j] += av[i] * bv4[j];
        }

        // Row max (reduce over this thread's 4 cols, then across tx via shfl)
        float tmax[4];
        #pragma unroll
        for (int i = 0; i < 4; i++) {
            tmax[i] = fmaxf(fmaxf(sv[i][0], sv[i][1]), fmaxf(sv[i][2], sv[i][3]));
        }
        #pragma unroll
        for (int msk = 1; msk < 16; msk <<= 1) {
            #pragma unroll
            for (int i = 0; i < 4; i++)
                tmax[i] = fmaxf(tmax[i], __shfl_xor_sync(0xffffffffu, tmax[i], msk));
        }

        float sc[4], rsum[4];
        #pragma unroll
        for (int i = 0; i < 4; i++) {
            const float mnew = fmaxf(m_i[i], tmax[i]);
            sc[i] = __expf(m_i[i] - mnew);
            m_i[i] = mnew;
            rsum[i] = 0.f;
            #pragma unroll
            for (int j = 0; j < 4; j++) {
                sv[i][j] = __expf(sv[i][j] - mnew);
                rsum[i] += sv[i][j];
            }
        }
        #pragma unroll
        for (int msk = 1; msk < 16; msk <<= 1) {
            #pragma unroll
            for (int i = 0; i < 4; i++)
                rsum[i] += __shfl_xor_sync(0xffffffffu, rsum[i], msk);
        }
        #pragma unroll
        for (int i = 0; i < 4; i++) {
            l_i[i] = l_i[i] * sc[i] + rsum[i];
            #pragma unroll
            for (int j = 0; j < 4; j++) o_acc[i][j] *= sc[i];
        }

        // Write P row-major (conflict-free float4 store per row)
        #pragma unroll
        for (int i = 0; i < 4; i++) {
            float4 pv4 = make_float4(sv[i][0], sv[i][1], sv[i][2], sv[i][3]);
            *(float4*)&Ps[ty * 4 + i][tx * 4] = pv4;
        }
        __syncthreads();

        // O += P @ V : inner over key index c, float4-blocked
        #pragma unroll 4
        for (int c4 = 0; c4 < 16; c4++) {
            float4 pr[4];
            #pragma unroll
            for (int i = 0; i < 4; i++)
                pr[i] = *(const float4*)&Ps[ty * 4 + i][c4 * 4];
            float4 vr[4];
            #pragma unroll
            for (int cc = 0; cc < 4; cc++)
                vr[cc] = *(const float4*)&Vs[c4 * 4 + cc][tx * 4];
            #pragma unroll
            for (int i = 0; i < 4; i++) {
                float pi[4] = {pr[i].x, pr[i].y, pr[i].z, pr[i].w};
                #pragma unroll
                for (int cc = 0; cc < 4; cc++) {
                    float vv[4] = {vr[cc].x, vr[cc].y, vr[cc].z, vr[cc].w};
                    #pragma unroll
                    for (int j = 0; j < 4; j++)
                        o_acc[i][j] += pi[cc] * vv[j];
                }
            }
        }
        __syncthreads();
    }

    // Epilogue: normalize and write to g_att [B*S, H*D]
    #pragma unroll
    for (int i = 0; i < 4; i++) {
        const float inv = 1.0f / l_i[i];
        const int s = qb * 64 + ty * 4 + i;
        float* orow = g_att + ((size_t)b * kS + s) * kHD + h * kD;
        #pragma unroll
        for (int j = 0; j < 4; j++)
            orow[tx * 4 + j] = o_acc[i][j] * inv;
    }
}

// ---------------------------------------------------------------------------
// Kernel 3: output projection. g_att[8192,1024] @ wo[1024,64] + bo -> out
// Grid: 128 blocks; each computes a 64x64 tile (full N). BK=16.
// ---------------------------------------------------------------------------
__global__ __launch_bounds__(256) void oproj_kernel(
    const float* __restrict__ wo, const float* __restrict__ bo,
    float* __restrict__ out)
{
    __shared__ float Xs[16][64];
    __shared__ float Ws[16][64];

    const int tid = threadIdx.x;
    const int tx = tid & 15;
    const int ty = tid >> 4;
    const int m0 = blockIdx.x * 64;

    const int xr  = tid >> 2;
    const int xc4 = tid & 3;
    const int wr  = tid >> 4;
    const int wc4 = tid & 15;

    float acc[4][4] = {};

    for (int kk = 0; kk < kHD; kk += 16) {
        float4 xv = *(const float4*)(g_att + (size_t)(m0 + xr) * kHD + kk + xc4 * 4);
        Xs[xc4 * 4 + 0][xr] = xv.x;
        Xs[xc4 * 4 + 1][xr] = xv.y;
        Xs[xc4 * 4 + 2][xr] = xv.z;
        Xs[xc4 * 4 + 3][xr] = xv.w;
        *(float4*)&Ws[wr][wc4 * 4] =
            *(const float4*)(wo + (size_t)(kk + wr) * kD + wc4 * 4);
        __syncthreads();

        #pragma unroll
        for (int k = 0; k < 16; k++) {
            float4 a = *(const float4*)&Xs[k][ty * 4];
            float4 b = *(const float4*)&Ws[k][tx * 4];
            float av[4] = {a.x, a.y, a.z, a.w};
            float bv4[4] = {b.x, b.y, b.z, b.w};
            #pragma unroll
            for (int i = 0; i < 4; i++)
                #pragma unroll
                for (int j = 0; j < 4; j++)
                    acc[i][j] += av[i] * bv4[j];
        }
        __syncthreads();
    }

    #pragma unroll
    for (int i = 0; i < 4; i++) {
        const int m = m0 + ty * 4 + i;
        #pragma unroll
        for (int j = 0; j < 4; j++) {
            const int d = tx * 4 + j;
            out[(size_t)m * kD + d] = acc[i][j] + bo[d];
        }
    }
}

// ---------------------------------------------------------------------------
extern "C" void kernel_launch(void* const* d_in, const int* in_sizes, int n_in,
                              void* d_out, int out_size)
{
    const float* x  = (const float*)d_in[0];
    const float* wq = (const float*)d_in[1];
    const float* bq = (const float*)d_in[2];
    const float* wk = (const float*)d_in[3];
    const float* bk = (const float*)d_in[4];
    const float* wv = (const float*)d_in[5];
    const float* bv = (const float*)d_in[6];
    const float* wo = (const float*)d_in[7];
    const float* bo = (const float*)d_in[8];
    float* out = (float*)d_out;

    qkv_kernel<<<dim3(kM / 64, 48), 256>>>(x, wq, bq, wk, bk, wv, bv);
    attn_kernel<<<dim3(kS / 64, kH, kB), 256>>>();
    oproj_kernel<<<dim3(kM / 64), 256>>>(wo, bo, out);
}